// round 1
// baseline (speedup 1.0000x reference)
#include <cuda_runtime.h>

#define BATCH   32768
#define WIDTH   256
#define NNODES  8
#define MT      64
#define NT      64
#define KT      16
#define NPART   2048   // (BATCH/MT) * (WIDTH/NT) = 512*4

// Scratch: unnormalized accumulators for internal nodes 1..6 (node 0 = x input,
// node 7 written straight to d_out). 6 * 32 MB static device arrays.
__device__ float g_acc[6][(size_t)BATCH * WIDTH];
__device__ float g_inv[NNODES];     // 1/||acc_i||_F per node
__device__ float g_part[NPART];     // per-CTA partial sum-of-squares

// ---------------------------------------------------------------------------
// Sum of squares of x (node 0), deterministic two-stage reduction.
// ---------------------------------------------------------------------------
__global__ __launch_bounds__(256) void sumsq_kernel(const float* __restrict__ x) {
    __shared__ float s[256];
    float acc = 0.f;
    const size_t n = (size_t)BATCH * WIDTH;
    for (size_t idx = (size_t)blockIdx.x * blockDim.x + threadIdx.x; idx < n;
         idx += (size_t)gridDim.x * blockDim.x) {
        float v = x[idx];
        acc += v * v;
    }
    s[threadIdx.x] = acc;
    __syncthreads();
    for (int o = 128; o > 0; o >>= 1) {
        if (threadIdx.x < o) s[threadIdx.x] += s[threadIdx.x + o];
        __syncthreads();
    }
    if (threadIdx.x == 0) g_part[blockIdx.x] = s[0];
}

// Reduce partials -> g_inv[node] = rsqrt(sum). Fixed-order => deterministic.
__global__ __launch_bounds__(256) void finalize_kernel(int node, int nparts) {
    __shared__ float s[256];
    float acc = 0.f;
    for (int i = threadIdx.x; i < nparts; i += 256) acc += g_part[i];
    s[threadIdx.x] = acc;
    __syncthreads();
    for (int o = 128; o > 0; o >>= 1) {
        if (threadIdx.x < o) s[threadIdx.x] += s[threadIdx.x + o];
        __syncthreads();
    }
    if (threadIdx.x == 0) g_inv[node] = rsqrtf(s[0]);
}

// ---------------------------------------------------------------------------
// Layer kernel for node j (1..7):
//   acc_j = sum_{i<j} relu( (acc_i @ W[e]) * inv_s_i + b[e] ),  e = j(j-1)/2 + i
// Each CTA: 64x64 output tile, 256 threads, 4x4 micro-tile per thread.
// Also emits per-CTA sum-of-squares partial for the node's norm.
// ---------------------------------------------------------------------------
__global__ __launch_bounds__(256) void layer_kernel(
    int j,
    const float* __restrict__ x,
    const float* __restrict__ Wt,
    const float* __restrict__ bias,
    float* __restrict__ out)
{
    __shared__ float As[KT][MT + 4];   // A tile, transposed: As[k][m]
    __shared__ float Bs[KT][NT + 4];   // B tile: Bs[k][n]
    __shared__ float red[256];

    const int tid = threadIdx.x;
    const int tx = tid & 15;           // n direction (16)
    const int ty = tid >> 4;           // m direction (16)
    const int m0 = blockIdx.x * MT;
    const int n0 = blockIdx.y * NT;
    const int base_e = j * (j - 1) / 2;

    float sum[4][4];
#pragma unroll
    for (int a = 0; a < 4; ++a)
#pragma unroll
        for (int c = 0; c < 4; ++c) sum[a][c] = 0.f;

    for (int i = 0; i < j; ++i) {
        const float* A = (i == 0) ? x : &g_acc[i - 1][0];
        const float inv_s = g_inv[i];
        const float* We = Wt + (size_t)(base_e + i) * WIDTH * WIDTH;
        const float* be = bias + (size_t)(base_e + i) * WIDTH;

        float acc[4][4];
#pragma unroll
        for (int a = 0; a < 4; ++a)
#pragma unroll
            for (int c = 0; c < 4; ++c) acc[a][c] = 0.f;

        for (int kt = 0; kt < WIDTH; kt += KT) {
            // Load A tile (64 m x 16 k), store transposed As[k][m]
#pragma unroll
            for (int r = 0; r < 4; ++r) {
                int m = (tid >> 4) + r * 16;
                int k = tid & 15;
                As[k][m] = A[(size_t)(m0 + m) * WIDTH + kt + k];
            }
            // Load B tile (16 k x 64 n), coalesced over n
#pragma unroll
            for (int r = 0; r < 4; ++r) {
                int k = (tid >> 6) + r * 4;
                int n = tid & 63;
                Bs[k][n] = We[(size_t)(kt + k) * WIDTH + n0 + n];
            }
            __syncthreads();
#pragma unroll
            for (int k = 0; k < KT; ++k) {
                float ra[4], rb[4];
#pragma unroll
                for (int a = 0; a < 4; ++a) ra[a] = As[k][ty * 4 + a];
#pragma unroll
                for (int c = 0; c < 4; ++c) rb[c] = Bs[k][tx * 4 + c];
#pragma unroll
                for (int a = 0; a < 4; ++a)
#pragma unroll
                    for (int c = 0; c < 4; ++c) acc[a][c] += ra[a] * rb[c];
            }
            __syncthreads();
        }

        // Edge epilogue: scale by 1/s_i, add bias, relu, accumulate into node sum
#pragma unroll
        for (int c = 0; c < 4; ++c) {
            float bv = be[n0 + tx * 4 + c];
#pragma unroll
            for (int a = 0; a < 4; ++a) {
                float v = acc[a][c] * inv_s + bv;
                sum[a][c] += fmaxf(v, 0.f);
            }
        }
    }

    // Destination: nodes 1..6 -> scratch, node 7 -> d_out (unnormalized acc_7)
    float* dst = (j <= 6) ? &g_acc[j - 1][0] : out;
    float ss = 0.f;
#pragma unroll
    for (int a = 0; a < 4; ++a)
#pragma unroll
        for (int c = 0; c < 4; ++c) {
            float v = sum[a][c];
            dst[(size_t)(m0 + ty * 4 + a) * WIDTH + n0 + tx * 4 + c] = v;
            ss += v * v;
        }

    red[tid] = ss;
    __syncthreads();
    for (int o = 128; o > 0; o >>= 1) {
        if (tid < o) red[tid] += red[tid + o];
        __syncthreads();
    }
    if (tid == 0) g_part[blockIdx.y * gridDim.x + blockIdx.x] = red[0];
}

// Final: out = acc_7 * (1/||acc_7||). (l2norm applied twice collapses to once.)
__global__ __launch_bounds__(256) void scale_kernel(float* __restrict__ out) {
    const float inv = g_inv[7];
    const size_t n = (size_t)BATCH * WIDTH;
    for (size_t idx = (size_t)blockIdx.x * blockDim.x + threadIdx.x; idx < n;
         idx += (size_t)gridDim.x * blockDim.x) {
        out[idx] *= inv;
    }
}

// ---------------------------------------------------------------------------
extern "C" void kernel_launch(void* const* d_in, const int* in_sizes, int n_in,
                              void* d_out, int out_size)
{
    // Defensive input identification by element count:
    //   x: 32768*256 = 8388608, W: 28*256*256 = 1835008, b: 28*256 = 7168
    const float* x = nullptr;
    const float* W = nullptr;
    const float* b = nullptr;
    for (int i = 0; i < n_in; ++i) {
        if (in_sizes[i] == BATCH * WIDTH)            x = (const float*)d_in[i];
        else if (in_sizes[i] == 28 * WIDTH * WIDTH)  W = (const float*)d_in[i];
        else if (in_sizes[i] == 28 * WIDTH)          b = (const float*)d_in[i];
    }
    float* out = (float*)d_out;

    // Node 0 norm
    sumsq_kernel<<<NPART, 256>>>(x);
    finalize_kernel<<<1, 256>>>(0, NPART);

    // Nodes 1..7
    dim3 grid(BATCH / MT, WIDTH / NT);   // (512, 4) = 2048 CTAs
    for (int j = 1; j < NNODES; ++j) {
        layer_kernel<<<grid, 256>>>(j, x, W, b, out);
        finalize_kernel<<<1, 256>>>(j, NPART);
    }

    // out = acc_7 / ||acc_7||
    scale_kernel<<<2048, 256>>>(out);
}

// round 3
// speedup vs baseline: 3.8903x; 3.8903x over previous
#include <cuda_runtime.h>
#include <cstdint>

#define BATCH   32768
#define WIDTH   256
#define NNODES  8
#define NEDGE   28
#define MT      128
#define NTT     128
#define STAGES  4
#define NPART_X 2048
#define NPART_L 512

// ---- device scratch -------------------------------------------------------
__device__ float g_acc[6][(size_t)BATCH * WIDTH];   // unnormalized acc, nodes 1..6
__device__ float g_Wt[NEDGE * WIDTH * WIDTH];       // W transposed: Wt[e][n][k]
__device__ float g_inv[NNODES];
__device__ float g_part[NPART_X];

// ---- smem layout ----------------------------------------------------------
// stage s: A tile (128 m x 32 k floats, 16KB) at s*32768, B tile (128 n x 32 k) at +16384
#define STG_BYTES 32768
#define SM_RED    (STAGES * STG_BYTES)
#define SMEM_BYTES (SM_RED + 256 * 4)

// ---- PTX helpers ----------------------------------------------------------
__device__ __forceinline__ uint32_t smem_u32(const void* p) {
    uint32_t a;
    asm("{ .reg .u64 t; cvta.to.shared.u64 t, %1; cvt.u32.u64 %0, t; }" : "=r"(a) : "l"(p));
    return a;
}
__device__ __forceinline__ void cp16(uint32_t dst, const void* src) {
    asm volatile("cp.async.cg.shared.global [%0], [%1], 16;" :: "r"(dst), "l"(src) : "memory");
}
__device__ __forceinline__ void cp_commit() {
    asm volatile("cp.async.commit_group;" ::: "memory");
}
template <int N> __device__ __forceinline__ void cp_wait() {
    asm volatile("cp.async.wait_group %0;" :: "n"(N) : "memory");
}
__device__ __forceinline__ void ldsm4(uint32_t* r, uint32_t a) {
    asm volatile("ldmatrix.sync.aligned.m8n8.x4.shared.b16 {%0,%1,%2,%3}, [%4];"
                 : "=r"(r[0]), "=r"(r[1]), "=r"(r[2]), "=r"(r[3]) : "r"(a));
}
__device__ __forceinline__ void mma8(float* c, const uint32_t* a, uint32_t b0, uint32_t b1) {
    asm volatile(
        "mma.sync.aligned.m16n8k8.row.col.f32.tf32.tf32.f32 "
        "{%0,%1,%2,%3}, {%4,%5,%6,%7}, {%8,%9}, {%0,%1,%2,%3};"
        : "+f"(c[0]), "+f"(c[1]), "+f"(c[2]), "+f"(c[3])
        : "r"(a[0]), "r"(a[1]), "r"(a[2]), "r"(a[3]), "r"(b0), "r"(b1));
}

// ---------------------------------------------------------------------------
// transpose: Wt[e][n][k] = W[e][k][n]
// ---------------------------------------------------------------------------
__global__ __launch_bounds__(256) void transpose_kernel(const float* __restrict__ W) {
    __shared__ float t[32][33];
    int e = blockIdx.z;
    int bx = blockIdx.x * 32, by = blockIdx.y * 32;
    const float* We = W + (size_t)e * WIDTH * WIDTH;
    float* Wte = g_Wt + (size_t)e * WIDTH * WIDTH;
    int x = threadIdx.x, y = threadIdx.y;  // block (32, 8)
#pragma unroll
    for (int r = 0; r < 32; r += 8) t[y + r][x] = We[(size_t)(by + y + r) * WIDTH + bx + x];
    __syncthreads();
#pragma unroll
    for (int r = 0; r < 32; r += 8) Wte[(size_t)(bx + y + r) * WIDTH + by + x] = t[x][y + r];
}

// ---------------------------------------------------------------------------
// sumsq of x, deterministic two-stage
// ---------------------------------------------------------------------------
__global__ __launch_bounds__(256) void sumsq_kernel(const float* __restrict__ x) {
    __shared__ float s[256];
    float acc = 0.f;
    const size_t n = (size_t)BATCH * WIDTH;
    for (size_t i = (size_t)blockIdx.x * 256 + threadIdx.x; i < n; i += (size_t)gridDim.x * 256) {
        float v = x[i];
        acc += v * v;
    }
    s[threadIdx.x] = acc;
    __syncthreads();
    for (int o = 128; o > 0; o >>= 1) {
        if (threadIdx.x < o) s[threadIdx.x] += s[threadIdx.x + o];
        __syncthreads();
    }
    if (threadIdx.x == 0) g_part[blockIdx.x] = s[0];
}

__global__ __launch_bounds__(256) void finalize_kernel(int node, int nparts) {
    __shared__ float s[256];
    float acc = 0.f;
    for (int i = threadIdx.x; i < nparts; i += 256) acc += g_part[i];
    s[threadIdx.x] = acc;
    __syncthreads();
    for (int o = 128; o > 0; o >>= 1) {
        if (threadIdx.x < o) s[threadIdx.x] += s[threadIdx.x + o];
        __syncthreads();
    }
    if (threadIdx.x == 0) g_inv[node] = rsqrtf(s[0]);
}

// ---------------------------------------------------------------------------
// Layer kernel: acc_j = sum_{i<j} relu((acc_i @ W[e]) * inv_i + b[e])
// mma.sync tf32 m16n8k8, CTA 128x128, 8 warps (2 m x 4 n), warp tile 64x32.
// cp.async 4-stage pipeline, k-tile 32. grid (2, 256).
// ---------------------------------------------------------------------------
__global__ __launch_bounds__(256, 1) void layer_kernel(
    int j,
    const float* __restrict__ x,
    const float* __restrict__ bias,
    float* __restrict__ out)
{
    extern __shared__ char smem[];
    const uint32_t sb = smem_u32(smem);
    const int tid = threadIdx.x;
    const int lane = tid & 31;
    const int wid = tid >> 5;
    const int wm = wid & 1;         // 0..1, 64 rows each
    const int wn = wid >> 1;        // 0..3, 32 cols each
    const int m0 = blockIdx.y * MT;
    const int n0 = blockIdx.x * NTT;
    const int base_e = j * (j - 1) / 2;

    const int g = lane >> 2;        // mma group row
    const int t = lane & 3;         // mma thread-in-group
    const int sel = lane >> 3;      // ldmatrix matrix id
    const int rr = lane & 7;        // ldmatrix row within matrix
    const int h = sel >> 1;         // k-granule half (0/1)

    // per-lane ldmatrix row byte-offsets within a stage
    uint32_t aoff[4], boff[2];
#pragma unroll
    for (int mf = 0; mf < 4; ++mf) {
        int arow = wm * 64 + mf * 16 + rr + (sel & 1) * 8;
        aoff[mf] = (uint32_t)(arow * 128);
    }
#pragma unroll
    for (int nf2 = 0; nf2 < 2; ++nf2) {
        int brow = wn * 32 + nf2 * 16 + rr + (sel & 1) * 8;
        boff[nf2] = (uint32_t)(16384 + brow * 128);
    }

    float C[4][4][4];
    float S[4][4][4];
#pragma unroll
    for (int a = 0; a < 4; ++a)
#pragma unroll
        for (int b = 0; b < 4; ++b)
#pragma unroll
            for (int c = 0; c < 4; ++c) S[a][b][c] = 0.f;

    const int T = j * 8;   // total k-tiles streamed

    auto load_tile = [&](int tt) {
        if (tt < T) {
            const int e = tt >> 3, kt = tt & 7;
            const char* Asrc = (const char*)((e == 0) ? x : g_acc[e - 1])
                               + (size_t)m0 * 1024 + (size_t)kt * 128;
            const char* Bsrc = (const char*)(g_Wt + (size_t)(base_e + e) * WIDTH * WIDTH)
                               + (size_t)n0 * 1024 + (size_t)kt * 128;
            const uint32_t sbase = sb + (uint32_t)(tt & (STAGES - 1)) * STG_BYTES;
#pragma unroll
            for (int q = 0; q < 4; ++q) {
                int c = q * 256 + tid;
                int r = c >> 3, u = c & 7;
                uint32_t sw = (uint32_t)(r * 128 + ((u ^ (r & 7)) << 4));
                cp16(sbase + sw, Asrc + (size_t)r * 1024 + u * 16);
                cp16(sbase + 16384 + sw, Bsrc + (size_t)r * 1024 + u * 16);
            }
        }
        cp_commit();
    };

    load_tile(0);
    load_tile(1);

    int tt = 0;
    for (int e = 0; e < j; ++e) {
#pragma unroll
        for (int a = 0; a < 4; ++a)
#pragma unroll
            for (int b = 0; b < 4; ++b)
#pragma unroll
                for (int c = 0; c < 4; ++c) C[a][b][c] = 0.f;

        for (int kt = 0; kt < 8; ++kt, ++tt) {
            load_tile(tt + 2);
            cp_wait<2>();
            __syncthreads();
            const uint32_t sbase = sb + (uint32_t)(tt & (STAGES - 1)) * STG_BYTES;
#pragma unroll
            for (int ks = 0; ks < 4; ++ks) {
                const uint32_t gsw = (uint32_t)(((2 * ks + h) ^ rr) << 4);
                uint32_t a[4][4], b[2][4];
#pragma unroll
                for (int mf = 0; mf < 4; ++mf) ldsm4(a[mf], sbase + aoff[mf] + gsw);
#pragma unroll
                for (int nf2 = 0; nf2 < 2; ++nf2) ldsm4(b[nf2], sbase + boff[nf2] + gsw);
#pragma unroll
                for (int mf = 0; mf < 4; ++mf)
#pragma unroll
                    for (int nf = 0; nf < 4; ++nf)
                        mma8(C[mf][nf], a[mf], b[nf >> 1][nf & 1], b[nf >> 1][2 + (nf & 1)]);
            }
        }

        // edge epilogue: scale by 1/||acc_e||, + bias, relu, accumulate
        const float inv = g_inv[e];
        const float* brow = bias + (size_t)(base_e + e) * WIDTH + n0 + wn * 32;
#pragma unroll
        for (int nf = 0; nf < 4; ++nf) {
            const float b0 = __ldg(brow + nf * 8 + 2 * t);
            const float b1 = __ldg(brow + nf * 8 + 2 * t + 1);
#pragma unroll
            for (int mf = 0; mf < 4; ++mf) {
                S[mf][nf][0] += fmaxf(fmaf(C[mf][nf][0], inv, b0), 0.f);
                S[mf][nf][1] += fmaxf(fmaf(C[mf][nf][1], inv, b1), 0.f);
                S[mf][nf][2] += fmaxf(fmaf(C[mf][nf][2], inv, b0), 0.f);
                S[mf][nf][3] += fmaxf(fmaf(C[mf][nf][3], inv, b1), 0.f);
            }
        }
    }

    // write result tile + per-lane sumsq
    float* dst = (j <= 6) ? &g_acc[j - 1][0] : out;
    float ss = 0.f;
#pragma unroll
    for (int mf = 0; mf < 4; ++mf) {
#pragma unroll
        for (int half = 0; half < 2; ++half) {
            const int row = m0 + wm * 64 + mf * 16 + g + half * 8;
            float* dr = dst + (size_t)row * WIDTH + n0 + wn * 32;
#pragma unroll
            for (int nf = 0; nf < 4; ++nf) {
                float v0 = S[mf][nf][half * 2];
                float v1 = S[mf][nf][half * 2 + 1];
                *reinterpret_cast<float2*>(dr + nf * 8 + 2 * t) = make_float2(v0, v1);
                ss += v0 * v0 + v1 * v1;
            }
        }
    }

    // block sum-of-squares partial
    float* red = reinterpret_cast<float*>(smem + SM_RED);
    red[tid] = ss;
    __syncthreads();
    for (int o = 128; o > 0; o >>= 1) {
        if (tid < o) red[tid] += red[tid + o];
        __syncthreads();
    }
    if (tid == 0) g_part[blockIdx.y * 2 + blockIdx.x] = red[0];
}

// ---------------------------------------------------------------------------
__global__ __launch_bounds__(256) void scale_kernel(float* __restrict__ out) {
    const float inv = g_inv[7];
    const size_t n = (size_t)BATCH * WIDTH;
    for (size_t i = (size_t)blockIdx.x * 256 + threadIdx.x; i < n; i += (size_t)gridDim.x * 256)
        out[i] *= inv;
}

// ---------------------------------------------------------------------------
extern "C" void kernel_launch(void* const* d_in, const int* in_sizes, int n_in,
                              void* d_out, int out_size)
{
    const float* x = nullptr;
    const float* W = nullptr;
    const float* b = nullptr;
    for (int i = 0; i < n_in; ++i) {
        if (in_sizes[i] == BATCH * WIDTH)                 x = (const float*)d_in[i];
        else if (in_sizes[i] == NEDGE * WIDTH * WIDTH)    W = (const float*)d_in[i];
        else if (in_sizes[i] == NEDGE * WIDTH)            b = (const float*)d_in[i];
    }
    float* out = (float*)d_out;

    static bool attr_set = false;
    if (!attr_set) {
        cudaFuncSetAttribute(layer_kernel, cudaFuncAttributeMaxDynamicSharedMemorySize, SMEM_BYTES);
        attr_set = true;
    }

    transpose_kernel<<<dim3(8, 8, NEDGE), dim3(32, 8)>>>(W);
    sumsq_kernel<<<NPART_X, 256>>>(x);
    finalize_kernel<<<1, 256>>>(0, NPART_X);

    dim3 grid(2, BATCH / MT);   // (2, 256) = 512 CTAs
    for (int j = 1; j < NNODES; ++j) {
        layer_kernel<<<grid, 256, SMEM_BYTES>>>(j, x, b, out);
        finalize_kernel<<<1, 256>>>(j, NPART_L);
    }
    scale_kernel<<<2048, 256>>>(out);
}

// round 6
// speedup vs baseline: 6.9628x; 1.7898x over previous
#include <cuda_runtime.h>
#include <cuda_bf16.h>
#include <cstdint>

#define BATCH   32768
#define WIDTH   256
#define NNODES  8
#define NEDGE   28
#define MT      128
#define NTT     128
#define KTILE   64
#define STAGES  4
#define NPART_X 2048
#define NPART_L 512

// ---- device scratch -------------------------------------------------------
__device__ __nv_bfloat16 g_acc[6][(size_t)BATCH * WIDTH];  // unnormalized acc, nodes 1..6
__device__ __nv_bfloat16 g_x0[(size_t)BATCH * WIDTH];      // x converted to bf16
__device__ __nv_bfloat16 g_Wt[NEDGE * WIDTH * WIDTH];      // W transposed bf16: Wt[e][n][k]
__device__ float g_inv[NNODES];
__device__ float g_part[NPART_X];

// ---- smem layout ----------------------------------------------------------
// stage: A tile (128 m x 64 k bf16, 16KB) + B tile (128 n x 64 k, 16KB) = 32KB
#define STG_BYTES 32768
#define SM_RED    (STAGES * STG_BYTES)
#define SMEM_BYTES (SM_RED + 256 * 4)

// ---- PTX helpers ----------------------------------------------------------
__device__ __forceinline__ uint32_t smem_u32(const void* p) {
    uint32_t a;
    asm("{ .reg .u64 t; cvta.to.shared.u64 t, %1; cvt.u32.u64 %0, t; }" : "=r"(a) : "l"(p));
    return a;
}
__device__ __forceinline__ void cp16(uint32_t dst, const void* src) {
    asm volatile("cp.async.cg.shared.global [%0], [%1], 16;" :: "r"(dst), "l"(src) : "memory");
}
__device__ __forceinline__ void cp_commit() {
    asm volatile("cp.async.commit_group;" ::: "memory");
}
template <int N> __device__ __forceinline__ void cp_wait() {
    asm volatile("cp.async.wait_group %0;" :: "n"(N) : "memory");
}
__device__ __forceinline__ void ldsm4(uint32_t* r, uint32_t a) {
    asm volatile("ldmatrix.sync.aligned.m8n8.x4.shared.b16 {%0,%1,%2,%3}, [%4];"
                 : "=r"(r[0]), "=r"(r[1]), "=r"(r[2]), "=r"(r[3]) : "r"(a));
}
__device__ __forceinline__ void mma16(float* c, const uint32_t* a, uint32_t b0, uint32_t b1) {
    asm volatile(
        "mma.sync.aligned.m16n8k16.row.col.f32.bf16.bf16.f32 "
        "{%0,%1,%2,%3}, {%4,%5,%6,%7}, {%8,%9}, {%0,%1,%2,%3};"
        : "+f"(c[0]), "+f"(c[1]), "+f"(c[2]), "+f"(c[3])
        : "r"(a[0]), "r"(a[1]), "r"(a[2]), "r"(a[3]), "r"(b0), "r"(b1));
}

// ---------------------------------------------------------------------------
// transpose + convert: Wt[e][n][k] = bf16(W[e][k][n])
// ---------------------------------------------------------------------------
__global__ __launch_bounds__(256) void transpose_kernel(const float* __restrict__ W) {
    __shared__ float t[32][33];
    int e = blockIdx.z;
    int bx = blockIdx.x * 32, by = blockIdx.y * 32;
    const float* We = W + (size_t)e * WIDTH * WIDTH;
    __nv_bfloat16* Wte = g_Wt + (size_t)e * WIDTH * WIDTH;
    int x = threadIdx.x, y = threadIdx.y;  // block (32, 8)
#pragma unroll
    for (int r = 0; r < 32; r += 8) t[y + r][x] = We[(size_t)(by + y + r) * WIDTH + bx + x];
    __syncthreads();
#pragma unroll
    for (int r = 0; r < 32; r += 8)
        Wte[(size_t)(bx + y + r) * WIDTH + by + x] = __float2bfloat16(t[x][y + r]);
}

// ---------------------------------------------------------------------------
// sumsq of x + bf16 conversion, deterministic two-stage
// ---------------------------------------------------------------------------
__global__ __launch_bounds__(256) void sumsq_kernel(const float* __restrict__ x) {
    __shared__ float s[256];
    float acc = 0.f;
    const size_t n = (size_t)BATCH * WIDTH;
    for (size_t i = (size_t)blockIdx.x * 256 + threadIdx.x; i < n; i += (size_t)gridDim.x * 256) {
        float v = x[i];
        g_x0[i] = __float2bfloat16(v);
        acc += v * v;
    }
    s[threadIdx.x] = acc;
    __syncthreads();
    for (int o = 128; o > 0; o >>= 1) {
        if (threadIdx.x < o) s[threadIdx.x] += s[threadIdx.x + o];
        __syncthreads();
    }
    if (threadIdx.x == 0) g_part[blockIdx.x] = s[0];
}

__global__ __launch_bounds__(256) void finalize_kernel(int node, int nparts) {
    __shared__ float s[256];
    float acc = 0.f;
    for (int i = threadIdx.x; i < nparts; i += 256) acc += g_part[i];
    s[threadIdx.x] = acc;
    __syncthreads();
    for (int o = 128; o > 0; o >>= 1) {
        if (threadIdx.x < o) s[threadIdx.x] += s[threadIdx.x + o];
        __syncthreads();
    }
    if (threadIdx.x == 0) g_inv[node] = rsqrtf(s[0]);
}

// ---------------------------------------------------------------------------
// Layer kernel: acc_j = sum_{i<j} relu((acc_i @ W[e]) * inv_i + b[e])
// mma.sync bf16 m16n8k16, CTA 128x128, 8 warps (2 m x 4 n), warp tile 64x32.
// cp.async 4-stage pipeline, k-tile 64. grid (2, 256).
// ---------------------------------------------------------------------------
__global__ __launch_bounds__(256, 1) void layer_kernel(
    int j,
    const float* __restrict__ bias,
    float* __restrict__ out)
{
    extern __shared__ char smem[];
    const uint32_t sb = smem_u32(smem);
    const int tid = threadIdx.x;
    const int lane = tid & 31;
    const int wid = tid >> 5;
    const int wm = wid & 1;         // 0..1, 64 rows each
    const int wn = wid >> 1;        // 0..3, 32 cols each
    const int m0 = blockIdx.y * MT;
    const int n0 = blockIdx.x * NTT;
    const int base_e = j * (j - 1) / 2;

    const int g = lane >> 2;        // mma group row
    const int t = lane & 3;         // mma thread-in-group
    const int sel = lane >> 3;      // ldmatrix matrix id
    const int rr = lane & 7;        // ldmatrix row within matrix
    const int h = sel >> 1;         // k 16B-granule half (0/1)

    // per-lane ldmatrix row byte-offsets within a stage (rows are 128B = 64 bf16)
    uint32_t aoff[4], boff[2];
#pragma unroll
    for (int mf = 0; mf < 4; ++mf) {
        int arow = wm * 64 + mf * 16 + rr + (sel & 1) * 8;
        aoff[mf] = (uint32_t)(arow * 128);
    }
#pragma unroll
    for (int nf2 = 0; nf2 < 2; ++nf2) {
        int brow = wn * 32 + nf2 * 16 + rr + (sel & 1) * 8;
        boff[nf2] = (uint32_t)(16384 + brow * 128);
    }

    float C[4][4][4];
    float S[4][4][4];
#pragma unroll
    for (int a = 0; a < 4; ++a)
#pragma unroll
        for (int b = 0; b < 4; ++b)
#pragma unroll
            for (int c = 0; c < 4; ++c) S[a][b][c] = 0.f;

    const int T = j * 4;   // k-tiles streamed (4 per edge at KTILE=64)

    auto load_tile = [&](int tt) {
        if (tt < T) {
            const int e = tt >> 2, kt = tt & 3;
            const char* Asrc = (const char*)((e == 0) ? g_x0 : g_acc[e - 1])
                               + (size_t)m0 * 512 + (size_t)kt * 128;
            const char* Bsrc = (const char*)(g_Wt + (size_t)(base_e + e) * WIDTH * WIDTH)
                               + (size_t)n0 * 512 + (size_t)kt * 128;
            const uint32_t sbase = sb + (uint32_t)(tt & (STAGES - 1)) * STG_BYTES;
#pragma unroll
            for (int q = 0; q < 4; ++q) {
                int c = q * 256 + tid;
                int r = c >> 3, u = c & 7;
                uint32_t sw = (uint32_t)(r * 128 + ((u ^ (r & 7)) << 4));
                cp16(sbase + sw, Asrc + (size_t)r * 512 + u * 16);
                cp16(sbase + 16384 + sw, Bsrc + (size_t)r * 512 + u * 16);
            }
        }
        cp_commit();
    };

    load_tile(0);
    load_tile(1);

    int tt = 0;
    for (int e = 0; e < j; ++e) {
#pragma unroll
        for (int a = 0; a < 4; ++a)
#pragma unroll
            for (int b = 0; b < 4; ++b)
#pragma unroll
                for (int c = 0; c < 4; ++c) C[a][b][c] = 0.f;

        for (int kt = 0; kt < 4; ++kt, ++tt) {
            load_tile(tt + 2);
            cp_wait<2>();
            __syncthreads();
            const uint32_t sbase = sb + (uint32_t)(tt & (STAGES - 1)) * STG_BYTES;
#pragma unroll
            for (int ks = 0; ks < 4; ++ks) {   // 4 kfrags of 16 => KTILE 64
                const uint32_t gsw = (uint32_t)(((2 * ks + h) ^ rr) << 4);
                uint32_t a[4][4], b[2][4];
#pragma unroll
                for (int mf = 0; mf < 4; ++mf) ldsm4(a[mf], sbase + aoff[mf] + gsw);
#pragma unroll
                for (int nf2 = 0; nf2 < 2; ++nf2) ldsm4(b[nf2], sbase + boff[nf2] + gsw);
#pragma unroll
                for (int mf = 0; mf < 4; ++mf)
#pragma unroll
                    for (int nf = 0; nf < 4; ++nf)
                        mma16(C[mf][nf], a[mf], b[nf >> 1][nf & 1], b[nf >> 1][2 + (nf & 1)]);
            }
        }

        // edge epilogue: scale by 1/||acc_e||, + bias, relu, accumulate
        const float inv = g_inv[e];
        const float* brow = bias + (size_t)(base_e + e) * WIDTH + n0 + wn * 32;
#pragma unroll
        for (int nf = 0; nf < 4; ++nf) {
            const float b0 = __ldg(brow + nf * 8 + 2 * t);
            const float b1 = __ldg(brow + nf * 8 + 2 * t + 1);
#pragma unroll
            for (int mf = 0; mf < 4; ++mf) {
                S[mf][nf][0] += fmaxf(fmaf(C[mf][nf][0], inv, b0), 0.f);
                S[mf][nf][1] += fmaxf(fmaf(C[mf][nf][1], inv, b1), 0.f);
                S[mf][nf][2] += fmaxf(fmaf(C[mf][nf][2], inv, b0), 0.f);
                S[mf][nf][3] += fmaxf(fmaf(C[mf][nf][3], inv, b1), 0.f);
            }
        }
    }

    // write result tile + per-lane sumsq
    float ss = 0.f;
    if (j <= 6) {
        __nv_bfloat16* dst = &g_acc[j - 1][0];
#pragma unroll
        for (int mf = 0; mf < 4; ++mf) {
#pragma unroll
            for (int half = 0; half < 2; ++half) {
                const int row = m0 + wm * 64 + mf * 16 + g + half * 8;
                __nv_bfloat16* dr = dst + (size_t)row * WIDTH + n0 + wn * 32;
#pragma unroll
                for (int nf = 0; nf < 4; ++nf) {
                    float v0 = S[mf][nf][half * 2];
                    float v1 = S[mf][nf][half * 2 + 1];
                    *reinterpret_cast<__nv_bfloat162*>(dr + nf * 8 + 2 * t) =
                        __floats2bfloat162_rn(v0, v1);
                    ss += v0 * v0 + v1 * v1;
                }
            }
        }
    } else {
        float* dst = out;
#pragma unroll
        for (int mf = 0; mf < 4; ++mf) {
#pragma unroll
            for (int half = 0; half < 2; ++half) {
                const int row = m0 + wm * 64 + mf * 16 + g + half * 8;
                float* dr = dst + (size_t)row * WIDTH + n0 + wn * 32;
#pragma unroll
                for (int nf = 0; nf < 4; ++nf) {
                    float v0 = S[mf][nf][half * 2];
                    float v1 = S[mf][nf][half * 2 + 1];
                    *reinterpret_cast<float2*>(dr + nf * 8 + 2 * t) = make_float2(v0, v1);
                    ss += v0 * v0 + v1 * v1;
                }
            }
        }
    }

    // block sum-of-squares partial
    float* red = reinterpret_cast<float*>(smem + SM_RED);
    red[tid] = ss;
    __syncthreads();
    for (int o = 128; o > 0; o >>= 1) {
        if (tid < o) red[tid] += red[tid + o];
        __syncthreads();
    }
    if (tid == 0) g_part[blockIdx.y * 2 + blockIdx.x] = red[0];
}

// ---------------------------------------------------------------------------
__global__ __launch_bounds__(256) void scale_kernel(float* __restrict__ out) {
    const float inv = g_inv[7];
    const size_t n = (size_t)BATCH * WIDTH;
    for (size_t i = (size_t)blockIdx.x * 256 + threadIdx.x; i < n; i += (size_t)gridDim.x * 256)
        out[i] *= inv;
}

// ---------------------------------------------------------------------------
extern "C" void kernel_launch(void* const* d_in, const int* in_sizes, int n_in,
                              void* d_out, int out_size)
{
    const float* x = nullptr;
    const float* W = nullptr;
    const float* b = nullptr;
    for (int i = 0; i < n_in; ++i) {
        if (in_sizes[i] == BATCH * WIDTH)                 x = (const float*)d_in[i];
        else if (in_sizes[i] == NEDGE * WIDTH * WIDTH)    W = (const float*)d_in[i];
        else if (in_sizes[i] == NEDGE * WIDTH)            b = (const float*)d_in[i];
    }
    float* out = (float*)d_out;

    static bool attr_set = false;
    if (!attr_set) {
        cudaFuncSetAttribute(layer_kernel, cudaFuncAttributeMaxDynamicSharedMemorySize, SMEM_BYTES);
        attr_set = true;
    }

    transpose_kernel<<<dim3(8, 8, NEDGE), dim3(32, 8)>>>(W);
    sumsq_kernel<<<NPART_X, 256>>>(x);
    finalize_kernel<<<1, 256>>>(0, NPART_X);

    dim3 grid(2, BATCH / MT);   // (2, 256) = 512 CTAs
    for (int j = 1; j < NNODES; ++j) {
        layer_kernel<<<grid, 256, SMEM_BYTES>>>(j, b, out);
        finalize_kernel<<<1, 256>>>(j, NPART_L);
    }
    scale_kernel<<<2048, 256>>>(out);
}

// round 7
// speedup vs baseline: 7.0746x; 1.0161x over previous
#include <cuda_runtime.h>
#include <cuda_bf16.h>
#include <cstdint>

#define BATCH   32768
#define WIDTH   256
#define NNODES  8
#define NEDGE   28
#define MT      128
#define NTT     128
#define STAGES  4
#define NPART   512

// ---- device scratch -------------------------------------------------------
__device__ __nv_bfloat16 g_acc[6][(size_t)BATCH * WIDTH];  // unnormalized acc, nodes 1..6
__device__ __nv_bfloat16 g_x0[(size_t)BATCH * WIDTH];      // x converted to bf16
__device__ __nv_bfloat16 g_Wt[NEDGE * WIDTH * WIDTH];      // W transposed bf16: Wt[e][n][k]
__device__ float g_part[NNODES][NPART];                    // per-node sumsq partials

// ---- smem layout ----------------------------------------------------------
// stage: A tile (128 m x 64 k bf16, 16KB) + B tile (128 n x 64 k, 16KB) = 32KB
#define STG_BYTES 32768
#define SM_RED    (STAGES * STG_BYTES)
#define SM_INV    (SM_RED + 512 * 4)
#define SMEM_BYTES (SM_INV + 8 * 4)

// ---- PTX helpers ----------------------------------------------------------
__device__ __forceinline__ uint32_t smem_u32(const void* p) {
    uint32_t a;
    asm("{ .reg .u64 t; cvta.to.shared.u64 t, %1; cvt.u32.u64 %0, t; }" : "=r"(a) : "l"(p));
    return a;
}
__device__ __forceinline__ void cp16(uint32_t dst, const void* src) {
    asm volatile("cp.async.cg.shared.global [%0], [%1], 16;" :: "r"(dst), "l"(src) : "memory");
}
__device__ __forceinline__ void cp_commit() {
    asm volatile("cp.async.commit_group;" ::: "memory");
}
template <int N> __device__ __forceinline__ void cp_wait() {
    asm volatile("cp.async.wait_group %0;" :: "n"(N) : "memory");
}
__device__ __forceinline__ void ldsm4(uint32_t* r, uint32_t a) {
    asm volatile("ldmatrix.sync.aligned.m8n8.x4.shared.b16 {%0,%1,%2,%3}, [%4];"
                 : "=r"(r[0]), "=r"(r[1]), "=r"(r[2]), "=r"(r[3]) : "r"(a));
}
__device__ __forceinline__ void mma16(float* c, const uint32_t* a, uint32_t b0, uint32_t b1) {
    asm volatile(
        "mma.sync.aligned.m16n8k16.row.col.f32.bf16.bf16.f32 "
        "{%0,%1,%2,%3}, {%4,%5,%6,%7}, {%8,%9}, {%0,%1,%2,%3};"
        : "+f"(c[0]), "+f"(c[1]), "+f"(c[2]), "+f"(c[3])
        : "r"(a[0]), "r"(a[1]), "r"(a[2]), "r"(a[3]), "r"(b0), "r"(b1));
}

// ---------------------------------------------------------------------------
// transpose + convert: Wt[e][n][k] = bf16(W[e][k][n])
// ---------------------------------------------------------------------------
__global__ __launch_bounds__(256) void transpose_kernel(const float* __restrict__ W) {
    __shared__ float t[32][33];
    int e = blockIdx.z;
    int bx = blockIdx.x * 32, by = blockIdx.y * 32;
    const float* We = W + (size_t)e * WIDTH * WIDTH;
    __nv_bfloat16* Wte = g_Wt + (size_t)e * WIDTH * WIDTH;
    int x = threadIdx.x, y = threadIdx.y;  // block (32, 8)
#pragma unroll
    for (int r = 0; r < 32; r += 8) t[y + r][x] = We[(size_t)(by + y + r) * WIDTH + bx + x];
    __syncthreads();
#pragma unroll
    for (int r = 0; r < 32; r += 8)
        Wte[(size_t)(bx + y + r) * WIDTH + by + x] = __float2bfloat16(t[x][y + r]);
}

// ---------------------------------------------------------------------------
// sumsq of x + bf16 conversion, deterministic two-stage (512 partials)
// ---------------------------------------------------------------------------
__global__ __launch_bounds__(256) void sumsq_kernel(const float* __restrict__ x) {
    __shared__ float s[256];
    float acc = 0.f;
    const size_t n = (size_t)BATCH * WIDTH;
    for (size_t i = (size_t)blockIdx.x * 256 + threadIdx.x; i < n; i += (size_t)gridDim.x * 256) {
        float v = x[i];
        g_x0[i] = __float2bfloat16(v);
        acc += v * v;
    }
    s[threadIdx.x] = acc;
    __syncthreads();
    for (int o = 128; o > 0; o >>= 1) {
        if (threadIdx.x < o) s[threadIdx.x] += s[threadIdx.x + o];
        __syncthreads();
    }
    if (threadIdx.x == 0) g_part[0][blockIdx.x] = s[0];
}

// ---------------------------------------------------------------------------
// Layer kernel: acc_j = sum_{i<j} relu((acc_i @ W[e]) * inv_i + b[e])
// mma.sync bf16 m16n8k16, CTA 128x128, 16 warps (4 m x 4 n), warp tile 32x32.
// Inline per-node norm reduction (no separate finalize kernel). grid (2, 256).
// ---------------------------------------------------------------------------
__global__ __launch_bounds__(512, 1) void layer_kernel(
    int j,
    const float* __restrict__ bias,
    float* __restrict__ out)
{
    extern __shared__ char smem[];
    const uint32_t sb = smem_u32(smem);
    float* s_inv = reinterpret_cast<float*>(smem + SM_INV);
    const int tid = threadIdx.x;
    const int lane = tid & 31;
    const int wid = tid >> 5;
    const int wm = wid & 3;         // 0..3, 32 rows each
    const int wn = wid >> 2;        // 0..3, 32 cols each
    const int m0 = blockIdx.y * MT;
    const int n0 = blockIdx.x * NTT;
    const int base_e = j * (j - 1) / 2;

    // ---- inline norm: warp e reduces g_part[e][0..511] -> s_inv[e] ----
    if (wid < j) {
        float acc = 0.f;
#pragma unroll
        for (int i = 0; i < NPART / 32; ++i) acc += g_part[wid][i * 32 + lane];
#pragma unroll
        for (int o = 16; o > 0; o >>= 1) acc += __shfl_xor_sync(0xFFFFFFFFu, acc, o);
        if (lane == 0) s_inv[wid] = rsqrtf(acc);
    }

    const int g = lane >> 2;        // mma group row
    const int t = lane & 3;         // mma thread-in-group
    const int sel = lane >> 3;      // ldmatrix matrix id
    const int rr = lane & 7;        // ldmatrix row within matrix
    const int h = sel >> 1;         // k 16B-granule half (0/1)

    // per-lane ldmatrix row byte-offsets within a stage (rows are 128B = 64 bf16)
    uint32_t aoff[2], boff[2];
#pragma unroll
    for (int mf = 0; mf < 2; ++mf) {
        int arow = wm * 32 + mf * 16 + rr + (sel & 1) * 8;
        aoff[mf] = (uint32_t)(arow * 128);
    }
#pragma unroll
    for (int nf2 = 0; nf2 < 2; ++nf2) {
        int brow = wn * 32 + nf2 * 16 + rr + (sel & 1) * 8;
        boff[nf2] = (uint32_t)(16384 + brow * 128);
    }

    float C[2][4][4];
    float S[2][4][4];
#pragma unroll
    for (int a = 0; a < 2; ++a)
#pragma unroll
        for (int b = 0; b < 4; ++b)
#pragma unroll
            for (int c = 0; c < 4; ++c) S[a][b][c] = 0.f;

    const int T = j * 4;   // k-tiles streamed (4 per edge at KTILE=64)

    auto load_tile = [&](int tt) {
        if (tt < T) {
            const int e = tt >> 2, kt = tt & 3;
            const char* Asrc = (const char*)((e == 0) ? g_x0 : g_acc[e - 1])
                               + (size_t)m0 * 512 + (size_t)kt * 128;
            const char* Bsrc = (const char*)(g_Wt + (size_t)(base_e + e) * WIDTH * WIDTH)
                               + (size_t)n0 * 512 + (size_t)kt * 128;
            const uint32_t sbase = sb + (uint32_t)(tt & (STAGES - 1)) * STG_BYTES;
#pragma unroll
            for (int q = 0; q < 2; ++q) {
                int c = q * 512 + tid;
                int r = c >> 3, u = c & 7;
                uint32_t sw = (uint32_t)(r * 128 + ((u ^ (r & 7)) << 4));
                cp16(sbase + sw, Asrc + (size_t)r * 512 + u * 16);
                cp16(sbase + 16384 + sw, Bsrc + (size_t)r * 512 + u * 16);
            }
        }
        cp_commit();
    };

    load_tile(0);
    load_tile(1);

    int tt = 0;
    for (int e = 0; e < j; ++e) {
#pragma unroll
        for (int a = 0; a < 2; ++a)
#pragma unroll
            for (int b = 0; b < 4; ++b)
#pragma unroll
                for (int c = 0; c < 4; ++c) C[a][b][c] = 0.f;

        for (int kt = 0; kt < 4; ++kt, ++tt) {
            load_tile(tt + 2);
            cp_wait<2>();
            __syncthreads();
            const uint32_t sbase = sb + (uint32_t)(tt & (STAGES - 1)) * STG_BYTES;
#pragma unroll
            for (int ks = 0; ks < 4; ++ks) {   // 4 kfrags of 16 => KTILE 64
                const uint32_t gsw = (uint32_t)(((2 * ks + h) ^ rr) << 4);
                uint32_t a[2][4], b[2][4];
#pragma unroll
                for (int mf = 0; mf < 2; ++mf) ldsm4(a[mf], sbase + aoff[mf] + gsw);
#pragma unroll
                for (int nf2 = 0; nf2 < 2; ++nf2) ldsm4(b[nf2], sbase + boff[nf2] + gsw);
#pragma unroll
                for (int mf = 0; mf < 2; ++mf)
#pragma unroll
                    for (int nf = 0; nf < 4; ++nf)
                        mma16(C[mf][nf], a[mf], b[nf >> 1][nf & 1], b[nf >> 1][2 + (nf & 1)]);
            }
        }

        // edge epilogue: scale by 1/||acc_e||, + bias, relu, accumulate
        const float inv = s_inv[e];
        const float* brow = bias + (size_t)(base_e + e) * WIDTH + n0 + wn * 32;
#pragma unroll
        for (int nf = 0; nf < 4; ++nf) {
            const float b0 = __ldg(brow + nf * 8 + 2 * t);
            const float b1 = __ldg(brow + nf * 8 + 2 * t + 1);
#pragma unroll
            for (int mf = 0; mf < 2; ++mf) {
                S[mf][nf][0] += fmaxf(fmaf(C[mf][nf][0], inv, b0), 0.f);
                S[mf][nf][1] += fmaxf(fmaf(C[mf][nf][1], inv, b1), 0.f);
                S[mf][nf][2] += fmaxf(fmaf(C[mf][nf][2], inv, b0), 0.f);
                S[mf][nf][3] += fmaxf(fmaf(C[mf][nf][3], inv, b1), 0.f);
            }
        }
    }

    // write result tile + per-lane sumsq
    float ss = 0.f;
    if (j <= 6) {
        __nv_bfloat16* dst = &g_acc[j - 1][0];
#pragma unroll
        for (int mf = 0; mf < 2; ++mf) {
#pragma unroll
            for (int half = 0; half < 2; ++half) {
                const int row = m0 + wm * 32 + mf * 16 + g + half * 8;
                __nv_bfloat16* dr = dst + (size_t)row * WIDTH + n0 + wn * 32;
#pragma unroll
                for (int nf = 0; nf < 4; ++nf) {
                    float v0 = S[mf][nf][half * 2];
                    float v1 = S[mf][nf][half * 2 + 1];
                    *reinterpret_cast<__nv_bfloat162*>(dr + nf * 8 + 2 * t) =
                        __floats2bfloat162_rn(v0, v1);
                    ss += v0 * v0 + v1 * v1;
                }
            }
        }
    } else {
        float* dst = out;
#pragma unroll
        for (int mf = 0; mf < 2; ++mf) {
#pragma unroll
            for (int half = 0; half < 2; ++half) {
                const int row = m0 + wm * 32 + mf * 16 + g + half * 8;
                float* dr = dst + (size_t)row * WIDTH + n0 + wn * 32;
#pragma unroll
                for (int nf = 0; nf < 4; ++nf) {
                    float v0 = S[mf][nf][half * 2];
                    float v1 = S[mf][nf][half * 2 + 1];
                    *reinterpret_cast<float2*>(dr + nf * 8 + 2 * t) = make_float2(v0, v1);
                    ss += v0 * v0 + v1 * v1;
                }
            }
        }
    }

    // block sum-of-squares partial
    float* red = reinterpret_cast<float*>(smem + SM_RED);
    red[tid] = ss;
    __syncthreads();
    for (int o = 256; o > 0; o >>= 1) {
        if (tid < o) red[tid] += red[tid + o];
        __syncthreads();
    }
    if (tid == 0) g_part[j][blockIdx.y * 2 + blockIdx.x] = red[0];
}

// ---------------------------------------------------------------------------
// Final: out *= 1/||acc_7|| (double-l2norm collapses). Inline partial reduce.
// ---------------------------------------------------------------------------
__global__ __launch_bounds__(256) void scale_kernel(float* __restrict__ out) {
    __shared__ float s[256];
    s[threadIdx.x] = g_part[7][threadIdx.x] + g_part[7][threadIdx.x + 256];
    __syncthreads();
    for (int o = 128; o > 0; o >>= 1) {
        if (threadIdx.x < o) s[threadIdx.x] += s[threadIdx.x + o];
        __syncthreads();
    }
    const float inv = rsqrtf(s[0]);
    const size_t n = (size_t)BATCH * WIDTH;
    for (size_t i = (size_t)blockIdx.x * 256 + threadIdx.x; i < n; i += (size_t)gridDim.x * 256)
        out[i] *= inv;
}

// ---------------------------------------------------------------------------
extern "C" void kernel_launch(void* const* d_in, const int* in_sizes, int n_in,
                              void* d_out, int out_size)
{
    const float* x = nullptr;
    const float* W = nullptr;
    const float* b = nullptr;
    for (int i = 0; i < n_in; ++i) {
        if (in_sizes[i] == BATCH * WIDTH)                 x = (const float*)d_in[i];
        else if (in_sizes[i] == NEDGE * WIDTH * WIDTH)    W = (const float*)d_in[i];
        else if (in_sizes[i] == NEDGE * WIDTH)            b = (const float*)d_in[i];
    }
    float* out = (float*)d_out;

    static bool attr_set = false;
    if (!attr_set) {
        cudaFuncSetAttribute(layer_kernel, cudaFuncAttributeMaxDynamicSharedMemorySize, SMEM_BYTES);
        attr_set = true;
    }

    transpose_kernel<<<dim3(8, 8, NEDGE), dim3(32, 8)>>>(W);
    sumsq_kernel<<<NPART, 256>>>(x);

    dim3 grid(2, BATCH / MT);   // (2, 256) = 512 CTAs
    for (int j = 1; j < NNODES; ++j)
        layer_kernel<<<grid, 512, SMEM_BYTES>>>(j, b, out);

    scale_kernel<<<2048, 256>>>(out);
}